// round 15
// baseline (speedup 1.0000x reference)
#include <cuda_runtime.h>
#include <cuda_fp16.h>

#define NODES 50000
#define EDGES 800000
#define FDIM  96
#define CLS   40
#define CAP   64   // neighbor-bucket capacity (mean degree 16; P(>=64) ~ 1e-19)

// ---- scratch (static device globals; no allocation in kernel_launch) ----
// RULE (learned R6-R8): device globals are referenced ONLY inside device code.
// g_h16 rows are PRE-SCALED by dinv(row) in the GEMM epilogue, so aggregation
// is a pure unweighted gather-sum (out_i = di*(sum hscaled[s] + hscaled[i]) + b).
__device__ __half g_h16[(size_t)NODES * 96];   // dinv-scaled GEMM out (stride 96 = 192B rows)
__device__ __half g_a16[(size_t)NODES * 96];   // agg out / next GEMM in
__device__ __half g_x16[(size_t)NODES * 96];   // fp16 copy of input x
__device__ __half g_wt1[96 * 96];              // W1^T fp16  (wt[n*96+k] = W[k*96+n])
__device__ __half g_wt2[96 * 96];              // W2^T fp16
__device__ __half g_wtl[48 * 96];              // Wl^T fp16 padded to 48 rows (rows 40..47 = 0)
__device__ int    g_cnt[NODES];
__device__ int    g_coff[(size_t)NODES * CAP]; // per-slot BYTE offsets (src*192)

// ---------------- tiny counter zero (scatter-path prefix; split from k_prep
// so the scatter stream doesn't wait on the big converts) ----------------
__global__ void k_zero(int n) {
    int i = blockIdx.x * blockDim.x + threadIdx.x;
    if (i < n) g_cnt[i] = 0;
}

// ---------------- fp16 converts (gemm-path; no g_cnt touch) ----------------
__global__ void k_prep(const float* __restrict__ x,
                       const float* __restrict__ W1,
                       const float* __restrict__ W2,
                       const float* __restrict__ Wl, int N) {
    long i = (long)blockIdx.x * blockDim.x + threadIdx.x;
    long m = (long)N * 96;
    if (i < m) { g_x16[i] = __float2half(x[i]); return; }
    i -= m;
    if (i < 96 * 96) { int k = i / 96, n = i % 96; g_wt1[n * 96 + k] = __float2half(W1[i]); return; }
    i -= 96 * 96;
    if (i < 96 * 96) { int k = i / 96, n = i % 96; g_wt2[n * 96 + k] = __float2half(W2[i]); return; }
    i -= 96 * 96;
    if (i < 96 * 40) { int k = i / 40, n = i % 40; g_wtl[n * 96 + k] = __float2half(Wl[i]); }
}

// ---------------- bucketed scatter: store byte offsets directly ----------------
__global__ void k_scatter(const int* __restrict__ src, const int* __restrict__ dst, int e) {
    int i = blockIdx.x * blockDim.x + threadIdx.x;
    if (i < e) {
        int d = dst[i];
        int slot = atomicAdd(&g_cnt[d], 1);
        if (slot < CAP) g_coff[(size_t)d * CAP + slot] = src[i] * 192;
    }
}

// ---------------- tensor-core GEMM 96x96, dinv-scaled epilogue ----------------
__device__ __forceinline__ void mma16816(float& c0, float& c1, float& c2, float& c3,
                                         unsigned a0, unsigned a1, unsigned a2, unsigned a3,
                                         unsigned b0, unsigned b1) {
    asm volatile(
        "mma.sync.aligned.m16n8k16.row.col.f32.f16.f16.f32 "
        "{%0,%1,%2,%3}, {%4,%5,%6,%7}, {%8,%9}, {%0,%1,%2,%3};"
        : "+f"(c0), "+f"(c1), "+f"(c2), "+f"(c3)
        : "r"(a0), "r"(a1), "r"(a2), "r"(a3), "r"(b0), "r"(b1));
}

__global__ void __launch_bounds__(256)
k_gemm96t(int layer, int n) {
    __shared__ __align__(16) __half As[64 * 104];    // 13.3 KB
    __shared__ __align__(16) __half Bs[96 * 104];    // 20.0 KB
    const __half* __restrict__ A  = (layer == 0) ? g_x16 : g_a16;
    const __half* __restrict__ Wt = (layer == 0) ? g_wt1 : g_wt2;
    int tid = threadIdx.x;
    int row0 = blockIdx.x * 64;

    for (int i = tid; i < 96 * 12; i += 256) {
        int r = i / 12, c = i % 12;
        *(uint4*)&Bs[r * 104 + c * 8] = *(const uint4*)&Wt[r * 96 + c * 8];
    }
    for (int i = tid; i < 64 * 12; i += 256) {
        int r = i / 12, c = i % 12;
        uint4 v = make_uint4(0, 0, 0, 0);
        if (row0 + r < n) v = *(const uint4*)&A[(size_t)(row0 + r) * 96 + c * 8];
        *(uint4*)&As[r * 104 + c * 8] = v;
    }
    __syncthreads();

    int warp = tid >> 5, lane = tid & 31;
    int wm = warp & 1, wn = warp >> 1;
    int g = lane >> 2, q = (lane & 3) * 2;

    float c000, c001, c002, c003, c010, c011, c012, c013, c020, c021, c022, c023;
    float c100, c101, c102, c103, c110, c111, c112, c113, c120, c121, c122, c123;
    c000 = c001 = c002 = c003 = c010 = c011 = c012 = c013 = c020 = c021 = c022 = c023 = 0.f;
    c100 = c101 = c102 = c103 = c110 = c111 = c112 = c113 = c120 = c121 = c122 = c123 = 0.f;

#pragma unroll
    for (int ks = 0; ks < 6; ks++) {
        int k0 = ks * 16 + q;
        int mr = wm * 32 + g;
        unsigned a00 = *(const unsigned*)&As[mr * 104 + k0];
        unsigned a01 = *(const unsigned*)&As[(mr + 8) * 104 + k0];
        unsigned a02 = *(const unsigned*)&As[mr * 104 + k0 + 8];
        unsigned a03 = *(const unsigned*)&As[(mr + 8) * 104 + k0 + 8];
        unsigned a10 = *(const unsigned*)&As[(mr + 16) * 104 + k0];
        unsigned a11 = *(const unsigned*)&As[(mr + 24) * 104 + k0];
        unsigned a12 = *(const unsigned*)&As[(mr + 16) * 104 + k0 + 8];
        unsigned a13 = *(const unsigned*)&As[(mr + 24) * 104 + k0 + 8];

        int nr = wn * 24 + g;
        unsigned b0, b1;
        b0 = *(const unsigned*)&Bs[nr * 104 + k0];
        b1 = *(const unsigned*)&Bs[nr * 104 + k0 + 8];
        mma16816(c000, c001, c002, c003, a00, a01, a02, a03, b0, b1);
        mma16816(c100, c101, c102, c103, a10, a11, a12, a13, b0, b1);
        b0 = *(const unsigned*)&Bs[(nr + 8) * 104 + k0];
        b1 = *(const unsigned*)&Bs[(nr + 8) * 104 + k0 + 8];
        mma16816(c010, c011, c012, c013, a00, a01, a02, a03, b0, b1);
        mma16816(c110, c111, c112, c113, a10, a11, a12, a13, b0, b1);
        b0 = *(const unsigned*)&Bs[(nr + 16) * 104 + k0];
        b1 = *(const unsigned*)&Bs[(nr + 16) * 104 + k0 + 8];
        mma16816(c020, c021, c022, c023, a00, a01, a02, a03, b0, b1);
        mma16816(c120, c121, c122, c123, a10, a11, a12, a13, b0, b1);
    }

    // epilogue: scale each output row by dinv(row)=rsqrt(cnt+1), store fp16 stride 96
    int cbase = wn * 24 + q;
    int r0 = row0 + wm * 32 + g;
    int r0b = r0 + 8, r1 = r0 + 16, r1b = r0 + 24;
    float s0 = (r0 < n)  ? rsqrtf((float)(__ldg(&g_cnt[r0])  + 1)) : 0.f;
    float s1 = (r0b < n) ? rsqrtf((float)(__ldg(&g_cnt[r0b]) + 1)) : 0.f;
    float s2 = (r1 < n)  ? rsqrtf((float)(__ldg(&g_cnt[r1])  + 1)) : 0.f;
    float s3 = (r1b < n) ? rsqrtf((float)(__ldg(&g_cnt[r1b]) + 1)) : 0.f;
    if (r0 < n) {
        __half* hp = g_h16 + (size_t)r0 * 96;
        *(__half2*)&hp[cbase]      = __floats2half2_rn(s0 * c000, s0 * c001);
        *(__half2*)&hp[cbase + 8]  = __floats2half2_rn(s0 * c010, s0 * c011);
        *(__half2*)&hp[cbase + 16] = __floats2half2_rn(s0 * c020, s0 * c021);
    }
    if (r0b < n) {
        __half* hp = g_h16 + (size_t)r0b * 96;
        *(__half2*)&hp[cbase]      = __floats2half2_rn(s1 * c002, s1 * c003);
        *(__half2*)&hp[cbase + 8]  = __floats2half2_rn(s1 * c012, s1 * c013);
        *(__half2*)&hp[cbase + 16] = __floats2half2_rn(s1 * c022, s1 * c023);
    }
    if (r1 < n) {
        __half* hp = g_h16 + (size_t)r1 * 96;
        *(__half2*)&hp[cbase]      = __floats2half2_rn(s2 * c100, s2 * c101);
        *(__half2*)&hp[cbase + 8]  = __floats2half2_rn(s2 * c110, s2 * c111);
        *(__half2*)&hp[cbase + 16] = __floats2half2_rn(s2 * c120, s2 * c121);
    }
    if (r1b < n) {
        __half* hp = g_h16 + (size_t)r1b * 96;
        *(__half2*)&hp[cbase]      = __floats2half2_rn(s3 * c102, s3 * c103);
        *(__half2*)&hp[cbase + 8]  = __floats2half2_rn(s3 * c112, s3 * c113);
        *(__half2*)&hp[cbase + 16] = __floats2half2_rn(s3 * c122, s3 * c123);
    }
}

// ---------------- aggregation: unweighted gather-sum, pairwise-HADD2 convert ----
// L2-bandwidth bound (~6 TB/s random gather); traffic is algorithmically minimal.
__global__ void __launch_bounds__(256)
k_agg(const float* __restrict__ bias, int n) {
    int w = (blockIdx.x * blockDim.x + threadIdx.x) >> 5;
    int lane = threadIdx.x & 31;
    if (w >= n) return;
    int cntw = __ldg(&g_cnt[w]);
    float di = rsqrtf((float)(cntw + 1));
    int cnt = cntw > CAP ? CAP : cntw;
    const int* __restrict__ off = g_coff + (size_t)w * CAP;
    const char* hb = (const char*)g_h16 + lane * 8;
    bool p = lane < 24;
    float a0 = 0.f, a1 = 0.f, a2 = 0.f, a3 = 0.f;
    float b0 = 0.f, b1 = 0.f, b2 = 0.f, b3 = 0.f;
    uint2 u0 = make_uint2(0, 0), u1 = u0, u2 = u0, u3 = u0;
    float2 f;
    int j = 0;
    for (; j + 4 <= cnt; j += 4) {
        int4 o = __ldg((const int4*)(off + j));   // uniform across warp
        if (p) {
            u0 = __ldg((const uint2*)(hb + o.x));
            u1 = __ldg((const uint2*)(hb + o.y));
            u2 = __ldg((const uint2*)(hb + o.z));
            u3 = __ldg((const uint2*)(hb + o.w));
        }
        __half2 sx0 = __hadd2(*reinterpret_cast<const __half2*>(&u0.x),
                              *reinterpret_cast<const __half2*>(&u1.x));
        __half2 sy0 = __hadd2(*reinterpret_cast<const __half2*>(&u0.y),
                              *reinterpret_cast<const __half2*>(&u1.y));
        __half2 sx1 = __hadd2(*reinterpret_cast<const __half2*>(&u2.x),
                              *reinterpret_cast<const __half2*>(&u3.x));
        __half2 sy1 = __hadd2(*reinterpret_cast<const __half2*>(&u2.y),
                              *reinterpret_cast<const __half2*>(&u3.y));
        f = __half22float2(sx0); a0 += f.x; a1 += f.y;
        f = __half22float2(sy0); a2 += f.x; a3 += f.y;
        f = __half22float2(sx1); b0 += f.x; b1 += f.y;
        f = __half22float2(sy1); b2 += f.x; b3 += f.y;
    }
    for (; j < cnt; j++) {
        int o = __ldg(off + j);
        if (p) u0 = __ldg((const uint2*)(hb + o));
        f = __half22float2(*reinterpret_cast<const __half2*>(&u0.x)); a0 += f.x; a1 += f.y;
        f = __half22float2(*reinterpret_cast<const __half2*>(&u0.y)); a2 += f.x; a3 += f.y;
    }
    // self term: hscaled[w] = di * h[w] already (full-precision convert)
    if (p) u0 = __ldg((const uint2*)(hb + (size_t)w * 192));
    f = __half22float2(*reinterpret_cast<const __half2*>(&u0.x)); a0 += f.x; a1 += f.y;
    f = __half22float2(*reinterpret_cast<const __half2*>(&u0.y)); a2 += f.x; a3 += f.y;
    a0 += b0; a1 += b1; a2 += b2; a3 += b3;
    if (p) {
        const float4 b4 = *reinterpret_cast<const float4*>(bias + 4 * lane);
        __half2 lo = __floats2half2_rn(fmaxf(di * a0 + b4.x, 0.f), fmaxf(di * a1 + b4.y, 0.f));
        __half2 hi = __floats2half2_rn(fmaxf(di * a2 + b4.z, 0.f), fmaxf(di * a3 + b4.w, 0.f));
        uint2 o;
        o.x = *reinterpret_cast<unsigned*>(&lo);
        o.y = *reinterpret_cast<unsigned*>(&hi);
        *reinterpret_cast<uint2*>(g_a16 + (size_t)w * 96 + 4 * lane) = o;
    }
}

// ---------------- tensor-core classifier: out[n,40] = a16[n,96] @ Wl[96,40] + bl ----
__global__ void __launch_bounds__(256)
k_gemm40t(const float* __restrict__ bias, float* __restrict__ out, int n) {
    __shared__ __align__(16) __half As[128 * 104];   // 26.6 KB
    __shared__ __align__(16) __half Bs[48 * 104];    // 10.0 KB
    int tid = threadIdx.x;
    int row0 = blockIdx.x * 128;

    for (int i = tid; i < 48 * 12; i += 256) {
        int r = i / 12, c = i % 12;
        *(uint4*)&Bs[r * 104 + c * 8] = *(const uint4*)&g_wtl[r * 96 + c * 8];
    }
    for (int i = tid; i < 128 * 12; i += 256) {
        int r = i / 12, c = i % 12;
        uint4 v = make_uint4(0, 0, 0, 0);
        if (row0 + r < n) v = *(const uint4*)&g_a16[(size_t)(row0 + r) * 96 + c * 8];
        *(uint4*)&As[r * 104 + c * 8] = v;
    }
    __syncthreads();

    int warp = tid >> 5, lane = tid & 31;
    int wm = warp & 3, wn = warp >> 2;
    int g = lane >> 2, q = (lane & 3) * 2;

    float c000, c001, c002, c003, c010, c011, c012, c013, c020, c021, c022, c023;
    float c100, c101, c102, c103, c110, c111, c112, c113, c120, c121, c122, c123;
    c000 = c001 = c002 = c003 = c010 = c011 = c012 = c013 = c020 = c021 = c022 = c023 = 0.f;
    c100 = c101 = c102 = c103 = c110 = c111 = c112 = c113 = c120 = c121 = c122 = c123 = 0.f;

#pragma unroll
    for (int ks = 0; ks < 6; ks++) {
        int k0 = ks * 16 + q;
        int mr = wm * 32 + g;
        unsigned a00 = *(const unsigned*)&As[mr * 104 + k0];
        unsigned a01 = *(const unsigned*)&As[(mr + 8) * 104 + k0];
        unsigned a02 = *(const unsigned*)&As[mr * 104 + k0 + 8];
        unsigned a03 = *(const unsigned*)&As[(mr + 8) * 104 + k0 + 8];
        unsigned a10 = *(const unsigned*)&As[(mr + 16) * 104 + k0];
        unsigned a11 = *(const unsigned*)&As[(mr + 24) * 104 + k0];
        unsigned a12 = *(const unsigned*)&As[(mr + 16) * 104 + k0 + 8];
        unsigned a13 = *(const unsigned*)&As[(mr + 24) * 104 + k0 + 8];

        int nr = wn * 24 + g;
        unsigned b0, b1;
        b0 = *(const unsigned*)&Bs[nr * 104 + k0];
        b1 = *(const unsigned*)&Bs[nr * 104 + k0 + 8];
        mma16816(c000, c001, c002, c003, a00, a01, a02, a03, b0, b1);
        mma16816(c100, c101, c102, c103, a10, a11, a12, a13, b0, b1);
        b0 = *(const unsigned*)&Bs[(nr + 8) * 104 + k0];
        b1 = *(const unsigned*)&Bs[(nr + 8) * 104 + k0 + 8];
        mma16816(c010, c011, c012, c013, a00, a01, a02, a03, b0, b1);
        mma16816(c110, c111, c112, c113, a10, a11, a12, a13, b0, b1);
        b0 = *(const unsigned*)&Bs[(nr + 16) * 104 + k0];
        b1 = *(const unsigned*)&Bs[(nr + 16) * 104 + k0 + 8];
        mma16816(c020, c021, c022, c023, a00, a01, a02, a03, b0, b1);
        mma16816(c120, c121, c122, c123, a10, a11, a12, a13, b0, b1);
    }

    int cbase = wn * 24 + q;
    float bv0 = (cbase < 40)      ? __ldg(&bias[cbase])      : 0.f;
    float bv1 = (cbase + 1 < 40)  ? __ldg(&bias[cbase + 1])  : 0.f;
    float bv8 = (cbase + 8 < 40)  ? __ldg(&bias[cbase + 8])  : 0.f;
    float bv9 = (cbase + 9 < 40)  ? __ldg(&bias[cbase + 9])  : 0.f;
    float bv16 = (cbase + 16 < 40) ? __ldg(&bias[cbase + 16]) : 0.f;
    float bv17 = (cbase + 17 < 40) ? __ldg(&bias[cbase + 17]) : 0.f;

#define GCN_ST(r, c, v, bv) do { if ((r) < n && (c) < 40) out[(size_t)(r) * 40 + (c)] = (v) + (bv); } while (0)
    int r0 = row0 + wm * 32 + g;
    GCN_ST(r0, cbase, c000, bv0);       GCN_ST(r0, cbase + 1, c001, bv1);
    GCN_ST(r0, cbase + 8, c010, bv8);   GCN_ST(r0, cbase + 9, c011, bv9);
    GCN_ST(r0, cbase + 16, c020, bv16); GCN_ST(r0, cbase + 17, c021, bv17);
    int r0b = r0 + 8;
    GCN_ST(r0b, cbase, c002, bv0);       GCN_ST(r0b, cbase + 1, c003, bv1);
    GCN_ST(r0b, cbase + 8, c012, bv8);   GCN_ST(r0b, cbase + 9, c013, bv9);
    GCN_ST(r0b, cbase + 16, c022, bv16); GCN_ST(r0b, cbase + 17, c023, bv17);
    int r1 = r0 + 16;
    GCN_ST(r1, cbase, c100, bv0);       GCN_ST(r1, cbase + 1, c101, bv1);
    GCN_ST(r1, cbase + 8, c110, bv8);   GCN_ST(r1, cbase + 9, c111, bv9);
    GCN_ST(r1, cbase + 16, c120, bv16); GCN_ST(r1, cbase + 17, c121, bv17);
    int r1b = r1 + 8;
    GCN_ST(r1b, cbase, c102, bv0);       GCN_ST(r1b, cbase + 1, c103, bv1);
    GCN_ST(r1b, cbase + 8, c112, bv8);   GCN_ST(r1b, cbase + 9, c113, bv9);
    GCN_ST(r1b, cbase + 16, c122, bv16); GCN_ST(r1b, cbase + 17, c123, bv17);
#undef GCN_ST
}

// ---------------- launch (forked capture: scatter path || prep+gemm0 path) ----
extern "C" void kernel_launch(void* const* d_in, const int* in_sizes, int n_in,
                              void* d_out, int out_size) {
    const float* x  = (const float*)d_in[0];
    const int*   ei = (const int*)d_in[1];
    const float* W1 = (const float*)d_in[2];
    const float* b1 = (const float*)d_in[3];
    const float* W2 = (const float*)d_in[4];
    const float* b2 = (const float*)d_in[5];
    const float* Wl = (const float*)d_in[6];
    const float* bl = (const float*)d_in[7];
    float* out = (float*)d_out;

    int N = in_sizes[0] / FDIM;
    int E = in_sizes[1] / 2;

    // one-time side-stream/event handles (host objects, not device memory)
    static cudaStream_t s1 = nullptr;
    static cudaEvent_t  eF = nullptr, eJ = nullptr;
    if (s1 == nullptr) {
        cudaStreamCreateWithFlags(&s1, cudaStreamNonBlocking);
        cudaEventCreateWithFlags(&eF, cudaEventDisableTiming);
        cudaEventCreateWithFlags(&eJ, cudaEventDisableTiming);
    }

    int gB = (N + 63) / 64;
    int aggB = (N + 7) / 8;
    long prepTotal = (long)N * 96 + 96 * 96 * 2 + 96 * 40;

    // fork: side stream does converts + layer-0 GEMM while main stream builds buckets
    cudaEventRecord(eF, 0);
    cudaStreamWaitEvent(s1, eF, 0);
    k_prep<<<(int)((prepTotal + 255) / 256), 256, 0, s1>>>(x, W1, W2, Wl, N);

    k_zero<<<(N + 255) / 256, 256>>>(N);
    k_scatter<<<(E + 255) / 256, 256>>>(ei, ei + E, E);

    // layer-0 GEMM reads g_cnt in its epilogue (dinv scaling) -> needs scatter done.
    // scatter finishes on stream 0; gemm96(0) goes after the join is not needed for
    // prep, but IS needed for cnt -> run gemm96(0) on s1 after waiting for stream 0.
    cudaEventRecord(eJ, 0);                 // scatter complete
    cudaStreamWaitEvent(s1, eJ, 0);
    k_gemm96t<<<gB, 256, 0, s1>>>(0, N);
    cudaEventRecord(eF, s1);                // gemm0 complete
    cudaStreamWaitEvent(0, eF, 0);

    // serial tail on main stream
    k_agg<<<aggB, 256>>>(b1, N);
    k_gemm96t<<<gB, 256>>>(1, N);
    k_agg<<<aggB, 256>>>(b2, N);
    k_gemm40t<<<(N + 127) / 128, 256>>>(bl, out, N);
}

// round 16
// speedup vs baseline: 1.0033x; 1.0033x over previous
#include <cuda_runtime.h>
#include <cuda_fp16.h>

#define NODES 50000
#define EDGES 800000
#define FDIM  96
#define CLS   40
#define CAP   64   // neighbor-bucket capacity (mean degree 16; P(>=64) ~ 1e-19)

// ---- scratch (static device globals; no allocation in kernel_launch) ----
// RULE (learned R6-R8): device globals are referenced ONLY inside device code.
// g_h16 rows are PRE-SCALED by dinv(row) in the GEMM epilogue, so aggregation
// is a pure unweighted gather-sum (out_i = di*(sum hscaled[s] + hscaled[i]) + b).
__device__ __half g_h16[(size_t)NODES * 96];   // dinv-scaled GEMM out (stride 96 = 192B rows)
__device__ __half g_a16[(size_t)NODES * 96];   // agg out / next GEMM in
__device__ __half g_x16[(size_t)NODES * 96];   // fp16 copy of input x
__device__ __half g_wt1[96 * 96];              // W1^T fp16  (wt[n*96+k] = W[k*96+n])
__device__ __half g_wt2[96 * 96];              // W2^T fp16
__device__ __half g_wtl[48 * 96];              // Wl^T fp16 padded to 48 rows (rows 40..47 = 0)
__device__ int    g_cnt[NODES];
__device__ int    g_coff[(size_t)NODES * CAP]; // per-slot BYTE offsets (src*192)

// ---------------- tiny counter zero (scatter-path prefix) ----------------
__global__ void k_zero(int n) {
    int i = blockIdx.x * blockDim.x + threadIdx.x;
    if (i < n) g_cnt[i] = 0;
}

// ---------------- fp16 converts (gemm-path; no g_cnt touch) ----------------
__global__ void k_prep(const float* __restrict__ x,
                       const float* __restrict__ W1,
                       const float* __restrict__ W2,
                       const float* __restrict__ Wl, int N) {
    long i = (long)blockIdx.x * blockDim.x + threadIdx.x;
    long m = (long)N * 96;
    if (i < m) { g_x16[i] = __float2half(x[i]); return; }
    i -= m;
    if (i < 96 * 96) { int k = i / 96, n = i % 96; g_wt1[n * 96 + k] = __float2half(W1[i]); return; }
    i -= 96 * 96;
    if (i < 96 * 96) { int k = i / 96, n = i % 96; g_wt2[n * 96 + k] = __float2half(W2[i]); return; }
    i -= 96 * 96;
    if (i < 96 * 40) { int k = i / 40, n = i % 40; g_wtl[n * 96 + k] = __float2half(Wl[i]); }
}

// ---------------- bucketed scatter: store byte offsets directly ----------------
__global__ void k_scatter(const int* __restrict__ src, const int* __restrict__ dst, int e) {
    int i = blockIdx.x * blockDim.x + threadIdx.x;
    if (i < e) {
        int d = dst[i];
        int slot = atomicAdd(&g_cnt[d], 1);
        if (slot < CAP) g_coff[(size_t)d * CAP + slot] = src[i] * 192;
    }
}

// ---------------- tensor-core GEMM 96x96, 128-row blocks, dinv-scaled epilogue ----
// R15 profile: 64-row blocks gave 15.5us/launch (tensor=10%, issue=29%) —
// preamble/B-reload dominated. 128-row blocks halve block count and B traffic.
// 8 warps = 4(m) x 2(n); warp tile 32m x 48n = 2 x 6 mma(m16n8k16) tiles.
__device__ __forceinline__ void mma16816(float& c0, float& c1, float& c2, float& c3,
                                         unsigned a0, unsigned a1, unsigned a2, unsigned a3,
                                         unsigned b0, unsigned b1) {
    asm volatile(
        "mma.sync.aligned.m16n8k16.row.col.f32.f16.f16.f32 "
        "{%0,%1,%2,%3}, {%4,%5,%6,%7}, {%8,%9}, {%0,%1,%2,%3};"
        : "+f"(c0), "+f"(c1), "+f"(c2), "+f"(c3)
        : "r"(a0), "r"(a1), "r"(a2), "r"(a3), "r"(b0), "r"(b1));
}

__global__ void __launch_bounds__(256)
k_gemm96t(int layer, int n) {
    __shared__ __align__(16) __half As[128 * 104];   // 26.6 KB
    __shared__ __align__(16) __half Bs[96 * 104];    // 20.0 KB
    const __half* __restrict__ A  = (layer == 0) ? g_x16 : g_a16;
    const __half* __restrict__ Wt = (layer == 0) ? g_wt1 : g_wt2;
    int tid = threadIdx.x;
    int row0 = blockIdx.x * 128;

    for (int i = tid; i < 96 * 12; i += 256) {
        int r = i / 12, c = i % 12;
        *(uint4*)&Bs[r * 104 + c * 8] = *(const uint4*)&Wt[r * 96 + c * 8];
    }
    for (int i = tid; i < 128 * 12; i += 256) {
        int r = i / 12, c = i % 12;
        uint4 v = make_uint4(0, 0, 0, 0);
        if (row0 + r < n) v = *(const uint4*)&A[(size_t)(row0 + r) * 96 + c * 8];
        *(uint4*)&As[r * 104 + c * 8] = v;
    }
    __syncthreads();

    int warp = tid >> 5, lane = tid & 31;
    int wm = warp & 3, wn = warp >> 2;         // wm 0..3 (32 rows each), wn 0..1 (48 cols each)
    int g = lane >> 2, q = (lane & 3) * 2;

    float acc[2][6][4];
#pragma unroll
    for (int mt = 0; mt < 2; mt++)
#pragma unroll
        for (int nt = 0; nt < 6; nt++)
#pragma unroll
            for (int r = 0; r < 4; r++) acc[mt][nt][r] = 0.f;

#pragma unroll
    for (int ks = 0; ks < 6; ks++) {
        int k0 = ks * 16 + q;
        int mr = wm * 32 + g;
        unsigned a00 = *(const unsigned*)&As[mr * 104 + k0];
        unsigned a01 = *(const unsigned*)&As[(mr + 8) * 104 + k0];
        unsigned a02 = *(const unsigned*)&As[mr * 104 + k0 + 8];
        unsigned a03 = *(const unsigned*)&As[(mr + 8) * 104 + k0 + 8];
        unsigned a10 = *(const unsigned*)&As[(mr + 16) * 104 + k0];
        unsigned a11 = *(const unsigned*)&As[(mr + 24) * 104 + k0];
        unsigned a12 = *(const unsigned*)&As[(mr + 16) * 104 + k0 + 8];
        unsigned a13 = *(const unsigned*)&As[(mr + 24) * 104 + k0 + 8];
#pragma unroll
        for (int nt = 0; nt < 6; nt++) {
            int nr = wn * 48 + nt * 8 + g;
            unsigned b0 = *(const unsigned*)&Bs[nr * 104 + k0];
            unsigned b1 = *(const unsigned*)&Bs[nr * 104 + k0 + 8];
            mma16816(acc[0][nt][0], acc[0][nt][1], acc[0][nt][2], acc[0][nt][3],
                     a00, a01, a02, a03, b0, b1);
            mma16816(acc[1][nt][0], acc[1][nt][1], acc[1][nt][2], acc[1][nt][3],
                     a10, a11, a12, a13, b0, b1);
        }
    }

    // epilogue: scale each output row by dinv(row)=rsqrt(cnt+1), store fp16 stride 96
    int cbase = wn * 48 + q;
#pragma unroll
    for (int mt = 0; mt < 2; mt++) {
        int ra = row0 + wm * 32 + mt * 16 + g;
        int rb = ra + 8;
        float sa = (ra < n) ? rsqrtf((float)(__ldg(&g_cnt[ra]) + 1)) : 0.f;
        float sb = (rb < n) ? rsqrtf((float)(__ldg(&g_cnt[rb]) + 1)) : 0.f;
        if (ra < n) {
            __half* hp = g_h16 + (size_t)ra * 96;
#pragma unroll
            for (int nt = 0; nt < 6; nt++)
                *(__half2*)&hp[cbase + nt * 8] =
                    __floats2half2_rn(sa * acc[mt][nt][0], sa * acc[mt][nt][1]);
        }
        if (rb < n) {
            __half* hp = g_h16 + (size_t)rb * 96;
#pragma unroll
            for (int nt = 0; nt < 6; nt++)
                *(__half2*)&hp[cbase + nt * 8] =
                    __floats2half2_rn(sb * acc[mt][nt][2], sb * acc[mt][nt][3]);
        }
    }
}

// ---------------- aggregation: unweighted gather-sum, pairwise-HADD2 convert ----
// L2-bandwidth bound (~6 TB/s random gather); traffic is algorithmically minimal.
__global__ void __launch_bounds__(256)
k_agg(const float* __restrict__ bias, int n) {
    int w = (blockIdx.x * blockDim.x + threadIdx.x) >> 5;
    int lane = threadIdx.x & 31;
    if (w >= n) return;
    int cntw = __ldg(&g_cnt[w]);
    float di = rsqrtf((float)(cntw + 1));
    int cnt = cntw > CAP ? CAP : cntw;
    const int* __restrict__ off = g_coff + (size_t)w * CAP;
    const char* hb = (const char*)g_h16 + lane * 8;
    bool p = lane < 24;
    float a0 = 0.f, a1 = 0.f, a2 = 0.f, a3 = 0.f;
    float b0 = 0.f, b1 = 0.f, b2 = 0.f, b3 = 0.f;
    uint2 u0 = make_uint2(0, 0), u1 = u0, u2 = u0, u3 = u0;
    float2 f;
    int j = 0;
    for (; j + 4 <= cnt; j += 4) {
        int4 o = __ldg((const int4*)(off + j));   // uniform across warp
        if (p) {
            u0 = __ldg((const uint2*)(hb + o.x));
            u1 = __ldg((const uint2*)(hb + o.y));
            u2 = __ldg((const uint2*)(hb + o.z));
            u3 = __ldg((const uint2*)(hb + o.w));
        }
        __half2 sx0 = __hadd2(*reinterpret_cast<const __half2*>(&u0.x),
                              *reinterpret_cast<const __half2*>(&u1.x));
        __half2 sy0 = __hadd2(*reinterpret_cast<const __half2*>(&u0.y),
                              *reinterpret_cast<const __half2*>(&u1.y));
        __half2 sx1 = __hadd2(*reinterpret_cast<const __half2*>(&u2.x),
                              *reinterpret_cast<const __half2*>(&u3.x));
        __half2 sy1 = __hadd2(*reinterpret_cast<const __half2*>(&u2.y),
                              *reinterpret_cast<const __half2*>(&u3.y));
        f = __half22float2(sx0); a0 += f.x; a1 += f.y;
        f = __half22float2(sy0); a2 += f.x; a3 += f.y;
        f = __half22float2(sx1); b0 += f.x; b1 += f.y;
        f = __half22float2(sy1); b2 += f.x; b3 += f.y;
    }
    for (; j < cnt; j++) {
        int o = __ldg(off + j);
        if (p) u0 = __ldg((const uint2*)(hb + o));
        f = __half22float2(*reinterpret_cast<const __half2*>(&u0.x)); a0 += f.x; a1 += f.y;
        f = __half22float2(*reinterpret_cast<const __half2*>(&u0.y)); a2 += f.x; a3 += f.y;
    }
    // self term: hscaled[w] = di * h[w] already (full-precision convert)
    if (p) u0 = __ldg((const uint2*)(hb + (size_t)w * 192));
    f = __half22float2(*reinterpret_cast<const __half2*>(&u0.x)); a0 += f.x; a1 += f.y;
    f = __half22float2(*reinterpret_cast<const __half2*>(&u0.y)); a2 += f.x; a3 += f.y;
    a0 += b0; a1 += b1; a2 += b2; a3 += b3;
    if (p) {
        const float4 b4 = *reinterpret_cast<const float4*>(bias + 4 * lane);
        __half2 lo = __floats2half2_rn(fmaxf(di * a0 + b4.x, 0.f), fmaxf(di * a1 + b4.y, 0.f));
        __half2 hi = __floats2half2_rn(fmaxf(di * a2 + b4.z, 0.f), fmaxf(di * a3 + b4.w, 0.f));
        uint2 o;
        o.x = *reinterpret_cast<unsigned*>(&lo);
        o.y = *reinterpret_cast<unsigned*>(&hi);
        *reinterpret_cast<uint2*>(g_a16 + (size_t)w * 96 + 4 * lane) = o;
    }
}

// ---------------- tensor-core classifier: out[n,40] = a16[n,96] @ Wl[96,40] + bl ----
__global__ void __launch_bounds__(256)
k_gemm40t(const float* __restrict__ bias, float* __restrict__ out, int n) {
    __shared__ __align__(16) __half As[128 * 104];   // 26.6 KB
    __shared__ __align__(16) __half Bs[48 * 104];    // 10.0 KB
    int tid = threadIdx.x;
    int row0 = blockIdx.x * 128;

    for (int i = tid; i < 48 * 12; i += 256) {
        int r = i / 12, c = i % 12;
        *(uint4*)&Bs[r * 104 + c * 8] = *(const uint4*)&g_wtl[r * 96 + c * 8];
    }
    for (int i = tid; i < 128 * 12; i += 256) {
        int r = i / 12, c = i % 12;
        uint4 v = make_uint4(0, 0, 0, 0);
        if (row0 + r < n) v = *(const uint4*)&g_a16[(size_t)(row0 + r) * 96 + c * 8];
        *(uint4*)&As[r * 104 + c * 8] = v;
    }
    __syncthreads();

    int warp = tid >> 5, lane = tid & 31;
    int wm = warp & 3, wn = warp >> 2;
    int g = lane >> 2, q = (lane & 3) * 2;

    float c000, c001, c002, c003, c010, c011, c012, c013, c020, c021, c022, c023;
    float c100, c101, c102, c103, c110, c111, c112, c113, c120, c121, c122, c123;
    c000 = c001 = c002 = c003 = c010 = c011 = c012 = c013 = c020 = c021 = c022 = c023 = 0.f;
    c100 = c101 = c102 = c103 = c110 = c111 = c112 = c113 = c120 = c121 = c122 = c123 = 0.f;

#pragma unroll
    for (int ks = 0; ks < 6; ks++) {
        int k0 = ks * 16 + q;
        int mr = wm * 32 + g;
        unsigned a00 = *(const unsigned*)&As[mr * 104 + k0];
        unsigned a01 = *(const unsigned*)&As[(mr + 8) * 104 + k0];
        unsigned a02 = *(const unsigned*)&As[mr * 104 + k0 + 8];
        unsigned a03 = *(const unsigned*)&As[(mr + 8) * 104 + k0 + 8];
        unsigned a10 = *(const unsigned*)&As[(mr + 16) * 104 + k0];
        unsigned a11 = *(const unsigned*)&As[(mr + 24) * 104 + k0];
        unsigned a12 = *(const unsigned*)&As[(mr + 16) * 104 + k0 + 8];
        unsigned a13 = *(const unsigned*)&As[(mr + 24) * 104 + k0 + 8];

        int nr = wn * 24 + g;
        unsigned b0, b1;
        b0 = *(const unsigned*)&Bs[nr * 104 + k0];
        b1 = *(const unsigned*)&Bs[nr * 104 + k0 + 8];
        mma16816(c000, c001, c002, c003, a00, a01, a02, a03, b0, b1);
        mma16816(c100, c101, c102, c103, a10, a11, a12, a13, b0, b1);
        b0 = *(const unsigned*)&Bs[(nr + 8) * 104 + k0];
        b1 = *(const unsigned*)&Bs[(nr + 8) * 104 + k0 + 8];
        mma16816(c010, c011, c012, c013, a00, a01, a02, a03, b0, b1);
        mma16816(c110, c111, c112, c113, a10, a11, a12, a13, b0, b1);
        b0 = *(const unsigned*)&Bs[(nr + 16) * 104 + k0];
        b1 = *(const unsigned*)&Bs[(nr + 16) * 104 + k0 + 8];
        mma16816(c020, c021, c022, c023, a00, a01, a02, a03, b0, b1);
        mma16816(c120, c121, c122, c123, a10, a11, a12, a13, b0, b1);
    }

    int cbase = wn * 24 + q;
    float bv0 = (cbase < 40)      ? __ldg(&bias[cbase])      : 0.f;
    float bv1 = (cbase + 1 < 40)  ? __ldg(&bias[cbase + 1])  : 0.f;
    float bv8 = (cbase + 8 < 40)  ? __ldg(&bias[cbase + 8])  : 0.f;
    float bv9 = (cbase + 9 < 40)  ? __ldg(&bias[cbase + 9])  : 0.f;
    float bv16 = (cbase + 16 < 40) ? __ldg(&bias[cbase + 16]) : 0.f;
    float bv17 = (cbase + 17 < 40) ? __ldg(&bias[cbase + 17]) : 0.f;

#define GCN_ST(r, c, v, bv) do { if ((r) < n && (c) < 40) out[(size_t)(r) * 40 + (c)] = (v) + (bv); } while (0)
    int r0 = row0 + wm * 32 + g;
    GCN_ST(r0, cbase, c000, bv0);       GCN_ST(r0, cbase + 1, c001, bv1);
    GCN_ST(r0, cbase + 8, c010, bv8);   GCN_ST(r0, cbase + 9, c011, bv9);
    GCN_ST(r0, cbase + 16, c020, bv16); GCN_ST(r0, cbase + 17, c021, bv17);
    int r0b = r0 + 8;
    GCN_ST(r0b, cbase, c002, bv0);       GCN_ST(r0b, cbase + 1, c003, bv1);
    GCN_ST(r0b, cbase + 8, c012, bv8);   GCN_ST(r0b, cbase + 9, c013, bv9);
    GCN_ST(r0b, cbase + 16, c022, bv16); GCN_ST(r0b, cbase + 17, c023, bv17);
    int r1 = r0 + 16;
    GCN_ST(r1, cbase, c100, bv0);       GCN_ST(r1, cbase + 1, c101, bv1);
    GCN_ST(r1, cbase + 8, c110, bv8);   GCN_ST(r1, cbase + 9, c111, bv9);
    GCN_ST(r1, cbase + 16, c120, bv16); GCN_ST(r1, cbase + 17, c121, bv17);
    int r1b = r1 + 8;
    GCN_ST(r1b, cbase, c102, bv0);       GCN_ST(r1b, cbase + 1, c103, bv1);
    GCN_ST(r1b, cbase + 8, c112, bv8);   GCN_ST(r1b, cbase + 9, c113, bv9);
    GCN_ST(r1b, cbase + 16, c122, bv16); GCN_ST(r1b, cbase + 17, c123, bv17);
#undef GCN_ST
}

// ---------------- launch (forked capture: scatter path || prep path) ----------
extern "C" void kernel_launch(void* const* d_in, const int* in_sizes, int n_in,
                              void* d_out, int out_size) {
    const float* x  = (const float*)d_in[0];
    const int*   ei = (const int*)d_in[1];
    const float* W1 = (const float*)d_in[2];
    const float* b1 = (const float*)d_in[3];
    const float* W2 = (const float*)d_in[4];
    const float* b2 = (const float*)d_in[5];
    const float* Wl = (const float*)d_in[6];
    const float* bl = (const float*)d_in[7];
    float* out = (float*)d_out;

    int N = in_sizes[0] / FDIM;
    int E = in_sizes[1] / 2;

    static cudaStream_t s1 = nullptr;
    static cudaEvent_t  eF = nullptr, eJ = nullptr;
    if (s1 == nullptr) {
        cudaStreamCreateWithFlags(&s1, cudaStreamNonBlocking);
        cudaEventCreateWithFlags(&eF, cudaEventDisableTiming);
        cudaEventCreateWithFlags(&eJ, cudaEventDisableTiming);
    }

    int gB = (N + 127) / 128;
    int aggB = (N + 7) / 8;
    long prepTotal = (long)N * 96 + 96 * 96 * 2 + 96 * 40;

    // fork: side stream does converts while main stream builds buckets
    cudaEventRecord(eF, 0);
    cudaStreamWaitEvent(s1, eF, 0);
    k_prep<<<(int)((prepTotal + 255) / 256), 256, 0, s1>>>(x, W1, W2, Wl, N);

    k_zero<<<(N + 255) / 256, 256>>>(N);
    k_scatter<<<(E + 255) / 256, 256>>>(ei, ei + E, E);

    // gemm96(0) needs g_cnt (epilogue dinv) AND g_x16/g_wt1 (prep)
    cudaEventRecord(eJ, 0);
    cudaStreamWaitEvent(s1, eJ, 0);
    k_gemm96t<<<gB, 256, 0, s1>>>(0, N);
    cudaEventRecord(eF, s1);
    cudaStreamWaitEvent(0, eF, 0);

    // serial tail on main stream
    k_agg<<<aggB, 256>>>(b1, N);
    k_gemm96t<<<gB, 256>>>(1, N);
    k_agg<<<aggB, 256>>>(b2, N);
    k_gemm40t<<<(N + 127) / 128, 256>>>(bl, out, N);
}